// round 1
// baseline (speedup 1.0000x reference)
#include <cuda_runtime.h>
#include <math.h>

#define B_  2
#define N_  2048
#define C_  512
#define H_  8
#define HD  64
#define BN_ (B_*N_)    // 4096 rows
#define BH_ (B_*H_)    // 16

// scale = 1/(S*sqrt(d_h)) = 1/(8*sqrt(8))
#define SCALE 0.04419417382415922f

// ---------------- scratch (device globals; no runtime allocation) ----------
__device__ float g_xn[(size_t)BN_ * C_];           // layernormed x  [4096,512]
__device__ float g_q [(size_t)BH_ * N_ * HD];      // [b,h,n,d]
__device__ float g_k [(size_t)BH_ * N_ * HD];
__device__ float g_v [(size_t)BH_ * N_ * HD];
__device__ float g_ao[(size_t)BH_ * N_ * HD];      // attention out [b,h,n,d]

// ---------------- LayerNorm: one block per row ------------------------------
__global__ __launch_bounds__(128) void ln_kernel(
    const float* __restrict__ x, const float* __restrict__ g,
    const float* __restrict__ bta, float* __restrict__ xn)
{
    int row = blockIdx.x;
    int tid = threadIdx.x;
    const float4* xr = reinterpret_cast<const float4*>(x + (size_t)row * C_);
    float4 v = xr[tid];
    float s  = v.x + v.y + v.z + v.w;
    float ss = v.x*v.x + v.y*v.y + v.z*v.z + v.w*v.w;
    #pragma unroll
    for (int o = 16; o; o >>= 1) {
        s  += __shfl_xor_sync(0xffffffffu, s,  o);
        ss += __shfl_xor_sync(0xffffffffu, ss, o);
    }
    __shared__ float sh[8];
    int w = tid >> 5, l = tid & 31;
    if (l == 0) { sh[w] = s; sh[4 + w] = ss; }
    __syncthreads();
    float st  = sh[0] + sh[1] + sh[2] + sh[3];
    float sst = sh[4] + sh[5] + sh[6] + sh[7];
    float mean = st * (1.0f / C_);
    float var  = sst * (1.0f / C_) - mean * mean;
    float r = rsqrtf(var + 1e-5f);
    float4 gg = reinterpret_cast<const float4*>(g)[tid];
    float4 bb = reinterpret_cast<const float4*>(bta)[tid];
    float4 o;
    o.x = (v.x - mean) * r * gg.x + bb.x;
    o.y = (v.y - mean) * r * gg.y + bb.y;
    o.z = (v.z - mean) * r * gg.z + bb.z;
    o.w = (v.w - mean) * r * gg.w + bb.w;
    reinterpret_cast<float4*>(xn + (size_t)row * C_)[tid] = o;
}

// ---------------- QKV GEMM: out[r][c] = sum_k xn[r][k]*W[k][c] + b[c] -------
// 64x64 tile, BK=16, 256 threads, 4x4 microtile. blockIdx.z selects q/k/v.
// Epilogue writes [b,h,n,d] layout (col tile == head since HD==64).
__global__ __launch_bounds__(256) void qkv_gemm(
    const float* __restrict__ A,
    const float* __restrict__ Wq, const float* __restrict__ Wk, const float* __restrict__ Wv,
    const float* __restrict__ bq, const float* __restrict__ bk, const float* __restrict__ bv,
    float* __restrict__ Q, float* __restrict__ K, float* __restrict__ V)
{
    const float* W; const float* bias; float* out;
    if (blockIdx.z == 0)      { W = Wq; bias = bq; out = Q; }
    else if (blockIdx.z == 1) { W = Wk; bias = bk; out = K; }
    else                      { W = Wv; bias = bv; out = V; }

    __shared__ float As[16][68];   // padded: conflict-light transposed store
    __shared__ float Bs[16][64];

    int tid = threadIdx.x;
    int tx = tid & 15, ty = tid >> 4;
    int rowbase = blockIdx.y * 64;
    int colbase = blockIdx.x * 64;

    float acc[4][4] = {};

    for (int k0 = 0; k0 < C_; k0 += 16) {
        #pragma unroll
        for (int i = tid; i < 1024; i += 256) {
            int r = i >> 4, c = i & 15;
            As[c][r] = A[(size_t)(rowbase + r) * C_ + k0 + c];
        }
        #pragma unroll
        for (int i = tid; i < 1024; i += 256) {
            int r = i >> 6, c = i & 63;
            Bs[r][c] = W[(size_t)(k0 + r) * C_ + colbase + c];
        }
        __syncthreads();
        #pragma unroll
        for (int kk = 0; kk < 16; kk++) {
            float a[4], b[4];
            #pragma unroll
            for (int i = 0; i < 4; i++) a[i] = As[kk][ty * 4 + i];
            #pragma unroll
            for (int j = 0; j < 4; j++) b[j] = Bs[kk][tx * 4 + j];
            #pragma unroll
            for (int i = 0; i < 4; i++)
                #pragma unroll
                for (int j = 0; j < 4; j++)
                    acc[i][j] += a[i] * b[j];
        }
        __syncthreads();
    }

    int h = blockIdx.x;  // 64-wide col tile == one head
    #pragma unroll
    for (int i = 0; i < 4; i++) {
        int r  = rowbase + ty * 4 + i;
        int b_ = r >> 11, n = r & (N_ - 1);
        float* op = out + (((size_t)b_ * H_ + h) * N_ + n) * HD;
        #pragma unroll
        for (int j = 0; j < 4; j++) {
            int d = tx * 4 + j;
            op[d] = acc[i][j] + bias[colbase + d];
        }
    }
}

// ---------------- Flash-style attention -------------------------------------
// grid: (N/128, B*H). 128 threads; each thread owns one query row.
// q and accumulator in registers, K/V tiles (32 keys x 64) in SMEM.
__global__ __launch_bounds__(128) void attn_kernel(
    const float* __restrict__ Q, const float* __restrict__ K,
    const float* __restrict__ V, const int* __restrict__ mask,
    float* __restrict__ O)
{
    int bh = blockIdx.y;
    int b  = bh >> 3;
    int qi = blockIdx.x * 128 + threadIdx.x;

    const float* qptr = Q + ((size_t)bh * N_ + qi) * HD;
    float q[HD];
    #pragma unroll
    for (int d = 0; d < HD; d++) q[d] = qptr[d] * SCALE;

    float acc[HD];
    #pragma unroll
    for (int d = 0; d < HD; d++) acc[d] = 0.0f;
    float m = -1e30f, l = 0.0f;

    __shared__ float ks[32 * HD];
    __shared__ float vs[32 * HD];
    __shared__ float msk[32];

    const size_t kvbase = (size_t)bh * N_ * HD;

    for (int kt = 0; kt < N_; kt += 32) {
        __syncthreads();
        const float4* ksrc = reinterpret_cast<const float4*>(K + kvbase + (size_t)kt * HD);
        const float4* vsrc = reinterpret_cast<const float4*>(V + kvbase + (size_t)kt * HD);
        #pragma unroll
        for (int i = threadIdx.x; i < 32 * HD / 4; i += 128) {
            reinterpret_cast<float4*>(ks)[i] = ksrc[i];
            reinterpret_cast<float4*>(vs)[i] = vsrc[i];
        }
        if (threadIdx.x < 32)
            msk[threadIdx.x] = mask[b * N_ + kt + threadIdx.x] ? 0.0f : -10000.0f;
        __syncthreads();

        float s[32];
        float tmax = -1e30f;
        #pragma unroll
        for (int j = 0; j < 32; j++) {
            float dot = 0.0f;
            const float4* k4 = reinterpret_cast<const float4*>(ks + j * HD);
            #pragma unroll
            for (int dd = 0; dd < HD / 4; dd++) {
                float4 kv = k4[dd];
                dot += q[4*dd + 0] * kv.x;
                dot += q[4*dd + 1] * kv.y;
                dot += q[4*dd + 2] * kv.z;
                dot += q[4*dd + 3] * kv.w;
            }
            dot += msk[j];
            s[j] = dot;
            tmax = fmaxf(tmax, dot);
        }
        float mnew = fmaxf(m, tmax);
        float corr = __expf(m - mnew);
        l *= corr;
        #pragma unroll
        for (int d = 0; d < HD; d++) acc[d] *= corr;
        #pragma unroll
        for (int j = 0; j < 32; j++) {
            float p = __expf(s[j] - mnew);
            l += p;
            const float4* v4 = reinterpret_cast<const float4*>(vs + j * HD);
            #pragma unroll
            for (int dd = 0; dd < HD / 4; dd++) {
                float4 vv = v4[dd];
                acc[4*dd + 0] += p * vv.x;
                acc[4*dd + 1] += p * vv.y;
                acc[4*dd + 2] += p * vv.z;
                acc[4*dd + 3] += p * vv.w;
            }
        }
        m = mnew;
    }

    float inv = 1.0f / l;
    float* optr = O + ((size_t)bh * N_ + qi) * HD;
    #pragma unroll
    for (int d = 0; d < HD; d++) optr[d] = acc[d] * inv;
}

// ---------------- Output projection GEMM -------------------------------------
// A logically [4096, 512] read from g_ao's [b,h,n,d] layout.
__global__ __launch_bounds__(256) void out_gemm(
    const float* __restrict__ A, const float* __restrict__ W,
    const float* __restrict__ bias, float* __restrict__ out)
{
    __shared__ float As[16][68];
    __shared__ float Bs[16][64];

    int tid = threadIdx.x;
    int tx = tid & 15, ty = tid >> 4;
    int rowbase = blockIdx.y * 64;
    int colbase = blockIdx.x * 64;

    float acc[4][4] = {};

    for (int k0 = 0; k0 < C_; k0 += 16) {
        #pragma unroll
        for (int i = tid; i < 1024; i += 256) {
            int r = rowbase + (i >> 4);
            int k = k0 + (i & 15);
            int b_ = r >> 11, n = r & (N_ - 1);
            int h  = k >> 6,  d = k & 63;
            As[i & 15][i >> 4] = A[(((size_t)b_ * H_ + h) * N_ + n) * HD + d];
        }
        #pragma unroll
        for (int i = tid; i < 1024; i += 256) {
            int r = i >> 6, c = i & 63;
            Bs[r][c] = W[(size_t)(k0 + r) * C_ + colbase + c];
        }
        __syncthreads();
        #pragma unroll
        for (int kk = 0; kk < 16; kk++) {
            float a[4], b[4];
            #pragma unroll
            for (int i = 0; i < 4; i++) a[i] = As[kk][ty * 4 + i];
            #pragma unroll
            for (int j = 0; j < 4; j++) b[j] = Bs[kk][tx * 4 + j];
            #pragma unroll
            for (int i = 0; i < 4; i++)
                #pragma unroll
                for (int j = 0; j < 4; j++)
                    acc[i][j] += a[i] * b[j];
        }
        __syncthreads();
    }

    #pragma unroll
    for (int i = 0; i < 4; i++) {
        int r = rowbase + ty * 4 + i;
        #pragma unroll
        for (int j = 0; j < 4; j++) {
            int c = colbase + tx * 4 + j;
            out[(size_t)r * C_ + c] = acc[i][j] + bias[c];
        }
    }
}

// ---------------- launch -----------------------------------------------------
extern "C" void kernel_launch(void* const* d_in, const int* in_sizes, int n_in,
                              void* d_out, int out_size)
{
    const float* x    = (const float*)d_in[0];
    const int*   mask = (const int*)  d_in[1];
    const float* ln_g = (const float*)d_in[2];
    const float* ln_b = (const float*)d_in[3];
    const float* wq   = (const float*)d_in[4];
    const float* bq   = (const float*)d_in[5];
    const float* wk   = (const float*)d_in[6];
    const float* bk   = (const float*)d_in[7];
    const float* wv   = (const float*)d_in[8];
    const float* bv   = (const float*)d_in[9];
    const float* wo   = (const float*)d_in[10];
    const float* bo   = (const float*)d_in[11];
    float* out = (float*)d_out;

    float *xn, *q, *k, *v, *ao;
    cudaGetSymbolAddress((void**)&xn, g_xn);
    cudaGetSymbolAddress((void**)&q,  g_q);
    cudaGetSymbolAddress((void**)&k,  g_k);
    cudaGetSymbolAddress((void**)&v,  g_v);
    cudaGetSymbolAddress((void**)&ao, g_ao);

    ln_kernel<<<BN_, 128>>>(x, ln_g, ln_b, xn);
    qkv_gemm<<<dim3(C_ / 64, BN_ / 64, 3), 256>>>(xn, wq, wk, wv, bq, bk, bv, q, k, v);
    attn_kernel<<<dim3(N_ / 128, BH_), 128>>>(q, k, v, mask, ao);
    out_gemm<<<dim3(C_ / 64, BN_ / 64), 256>>>(ao, wo, bo, out);
}

// round 2
// speedup vs baseline: 2.7398x; 2.7398x over previous
#include <cuda_runtime.h>
#include <math.h>
#include <stdint.h>

#define B_  2
#define N_  2048
#define C_  512
#define H_  8
#define HD  64
#define BN_ (B_*N_)    // 4096
#define BH_ (B_*H_)    // 16

// scale = 1/(S*sqrt(d_h)) = 1/(8*sqrt(8))
#define SCALE 0.04419417382415922f

// ---------------- scratch (device globals) ----------------------------------
__device__ float g_xn[(size_t)BN_ * C_];
__device__ float g_q [(size_t)BH_ * N_ * HD];
__device__ float g_k [(size_t)BH_ * N_ * HD];
__device__ float g_v [(size_t)BH_ * N_ * HD];
__device__ float g_ao[(size_t)BH_ * N_ * HD];

// ---------------- helpers ----------------------------------------------------
__device__ __forceinline__ uint32_t f2tf(float f) {
    uint32_t u;
    asm("cvt.rna.tf32.f32 %0, %1;" : "=r"(u) : "f"(f));
    return u;
}

__device__ __forceinline__ void mma_tf32(float c[4],
    uint32_t a0, uint32_t a1, uint32_t a2, uint32_t a3,
    uint32_t b0, uint32_t b1)
{
    asm volatile(
        "mma.sync.aligned.m16n8k8.row.col.f32.tf32.tf32.f32 "
        "{%0,%1,%2,%3}, {%4,%5,%6,%7}, {%8,%9}, {%0,%1,%2,%3};"
        : "+f"(c[0]), "+f"(c[1]), "+f"(c[2]), "+f"(c[3])
        : "r"(a0), "r"(a1), "r"(a2), "r"(a3), "r"(b0), "r"(b1));
}

// ---------------- LayerNorm ---------------------------------------------------
__global__ __launch_bounds__(128) void ln_kernel(
    const float* __restrict__ x, const float* __restrict__ g,
    const float* __restrict__ bta, float* __restrict__ xn)
{
    int row = blockIdx.x;
    int tid = threadIdx.x;
    const float4* xr = reinterpret_cast<const float4*>(x + (size_t)row * C_);
    float4 v = xr[tid];
    float s  = v.x + v.y + v.z + v.w;
    float ss = v.x*v.x + v.y*v.y + v.z*v.z + v.w*v.w;
    #pragma unroll
    for (int o = 16; o; o >>= 1) {
        s  += __shfl_xor_sync(0xffffffffu, s,  o);
        ss += __shfl_xor_sync(0xffffffffu, ss, o);
    }
    __shared__ float sh[8];
    int w = tid >> 5, l = tid & 31;
    if (l == 0) { sh[w] = s; sh[4 + w] = ss; }
    __syncthreads();
    float st  = sh[0] + sh[1] + sh[2] + sh[3];
    float sst = sh[4] + sh[5] + sh[6] + sh[7];
    float mean = st * (1.0f / C_);
    float var  = sst * (1.0f / C_) - mean * mean;
    float r = rsqrtf(var + 1e-5f);
    float4 gg = reinterpret_cast<const float4*>(g)[tid];
    float4 bb = reinterpret_cast<const float4*>(bta)[tid];
    float4 o;
    o.x = (v.x - mean) * r * gg.x + bb.x;
    o.y = (v.y - mean) * r * gg.y + bb.y;
    o.z = (v.z - mean) * r * gg.z + bb.z;
    o.w = (v.w - mean) * r * gg.w + bb.w;
    reinterpret_cast<float4*>(xn + (size_t)row * C_)[tid] = o;
}

// ---------------- QKV GEMM (tf32 mma): CTA 128x64, 8 warps (4Mx2N), BK=32 ----
__global__ __launch_bounds__(256) void qkv_gemm_t(
    const float* __restrict__ A,
    const float* __restrict__ Wq, const float* __restrict__ Wk, const float* __restrict__ Wv,
    const float* __restrict__ bq, const float* __restrict__ bk, const float* __restrict__ bv,
    float* __restrict__ Q, float* __restrict__ K, float* __restrict__ V)
{
    const float* W; const float* bias; float* out;
    if (blockIdx.z == 0)      { W = Wq; bias = bq; out = Q; }
    else if (blockIdx.z == 1) { W = Wk; bias = bk; out = K; }
    else                      { W = Wv; bias = bv; out = V; }

    __shared__ __align__(16) uint32_t As[128 * 36];
    __shared__ __align__(16) uint32_t Bs[64 * 36];

    int tid  = threadIdx.x;
    int lane = tid & 31;
    int wid  = tid >> 5;
    int wM = wid >> 1, wN = wid & 1;
    int g = lane >> 2, c = lane & 3;
    int rowbase = blockIdx.y * 128;
    int colbase = blockIdx.x * 64;

    float acc[2][4][4] = {};

    for (int k0 = 0; k0 < C_; k0 += 32) {
        __syncthreads();
        // A tile 128x32: float4 loads, tf32 convert, [row][k] stride 36
        #pragma unroll
        for (int p = 0; p < 4; p++) {
            int idx = tid + p * 256;
            int r = idx >> 3, k4 = idx & 7;
            float4 v = *reinterpret_cast<const float4*>(
                A + (size_t)(rowbase + r) * C_ + k0 + k4 * 4);
            uint4 t;
            t.x = f2tf(v.x); t.y = f2tf(v.y); t.z = f2tf(v.z); t.w = f2tf(v.w);
            *reinterpret_cast<uint4*>(As + r * 36 + k4 * 4) = t;
        }
        // B tile 32x64 transposed to [n][k] stride 36 (scalar stores)
        #pragma unroll
        for (int p = 0; p < 8; p++) {
            int idx = tid + p * 256;
            int n = idx & 63, kk = idx >> 6;
            float v = W[(size_t)(k0 + kk) * C_ + colbase + n];
            Bs[n * 36 + kk] = f2tf(v);
        }
        __syncthreads();

        #pragma unroll
        for (int ks = 0; ks < 4; ks++) {
            uint32_t a[2][4], b[4][2];
            #pragma unroll
            for (int mf = 0; mf < 2; mf++) {
                const uint32_t* ap = As + (wM * 32 + mf * 16 + g) * 36 + ks * 8;
                a[mf][0] = ap[c];
                a[mf][1] = ap[8 * 36 + c];
                a[mf][2] = ap[c + 4];
                a[mf][3] = ap[8 * 36 + c + 4];
            }
            #pragma unroll
            for (int nf = 0; nf < 4; nf++) {
                const uint32_t* bp = Bs + (wN * 32 + nf * 8 + g) * 36 + ks * 8;
                b[nf][0] = bp[c];
                b[nf][1] = bp[c + 4];
            }
            #pragma unroll
            for (int mf = 0; mf < 2; mf++)
                #pragma unroll
                for (int nf = 0; nf < 4; nf++)
                    mma_tf32(acc[mf][nf], a[mf][0], a[mf][1], a[mf][2], a[mf][3],
                             b[nf][0], b[nf][1]);
        }
    }

    // epilogue: write [b,h,n,d] (col tile of 64 == head h == blockIdx.x)
    int h = blockIdx.x;
    #pragma unroll
    for (int mf = 0; mf < 2; mf++) {
        int r0 = rowbase + wM * 32 + mf * 16 + g;
        #pragma unroll
        for (int nf = 0; nf < 4; nf++) {
            int d = wN * 32 + nf * 8 + 2 * c;
            float b0 = bias[colbase + d];
            float b1 = bias[colbase + d + 1];
            {
                int r = r0;
                int bb = r >> 11, n = r & (N_ - 1);
                float2 st = make_float2(acc[mf][nf][0] + b0, acc[mf][nf][1] + b1);
                *reinterpret_cast<float2*>(
                    out + (((size_t)bb * H_ + h) * N_ + n) * HD + d) = st;
            }
            {
                int r = r0 + 8;
                int bb = r >> 11, n = r & (N_ - 1);
                float2 st = make_float2(acc[mf][nf][2] + b0, acc[mf][nf][3] + b1);
                *reinterpret_cast<float2*>(
                    out + (((size_t)bb * H_ + h) * N_ + n) * HD + d) = st;
            }
        }
    }
}

// ---------------- Flash attention (tf32 mma) ---------------------------------
// CTA: 64 queries x full key loop; 4 warps, each owns 16 query rows.
// Q frags in regs; K tile [key][d]; V tile transposed [d][key]; P aliased on K.
__global__ __launch_bounds__(128) void attn_t(
    const float* __restrict__ Q, const float* __restrict__ K,
    const float* __restrict__ V, const int* __restrict__ mask,
    float* __restrict__ O)
{
    __shared__ __align__(16) uint32_t Ks[64 * 68];   // also reused as P
    __shared__ __align__(16) uint32_t Vs[64 * 68];   // transposed [d][key]
    __shared__ float ms[64];

    int bh = blockIdx.y;
    int b  = bh >> 3;
    int qbase = blockIdx.x * 64;
    int tid  = threadIdx.x;
    int wid  = tid >> 5, lane = tid & 31;
    int g = lane >> 2, c = lane & 3;
    int lr0 = wid * 16 + g;            // local query row (0..63)
    int r0  = qbase + lr0;             // global query row

    // Q fragments: rows r0, r0+8, all 64 dims (8 k-steps), scaled, tf32
    const float* Qp = Q + ((size_t)bh * N_ + r0) * HD;
    uint32_t qf[8][4];
    #pragma unroll
    for (int ks = 0; ks < 8; ks++) {
        qf[ks][0] = f2tf(Qp[ks * 8 + c] * SCALE);
        qf[ks][1] = f2tf(Qp[8 * HD + ks * 8 + c] * SCALE);
        qf[ks][2] = f2tf(Qp[ks * 8 + c + 4] * SCALE);
        qf[ks][3] = f2tf(Qp[8 * HD + ks * 8 + c + 4] * SCALE);
    }

    float of[8][4] = {};
    float m0 = -1e30f, m1 = -1e30f, l0 = 0.0f, l1 = 0.0f;
    const size_t kvb = (size_t)bh * N_ * HD;

    for (int kt = 0; kt < N_; kt += 64) {
        __syncthreads();   // prev-tile PV reads done before overwrite
        // K tile: [key][d], stride 68, float4 + tf32
        #pragma unroll
        for (int p = 0; p < 8; p++) {
            int idx = tid + p * 128;
            int j = idx >> 4, d4 = idx & 15;
            float4 v = *reinterpret_cast<const float4*>(
                K + kvb + (size_t)(kt + j) * HD + d4 * 4);
            uint4 t;
            t.x = f2tf(v.x); t.y = f2tf(v.y); t.z = f2tf(v.z); t.w = f2tf(v.w);
            *reinterpret_cast<uint4*>(Ks + j * 68 + d4 * 4) = t;
        }
        // V tile transposed: Vs[d][key], scalar stores
        #pragma unroll
        for (int p = 0; p < 32; p++) {
            int idx = tid + p * 128;
            int d = idx & 63, j = idx >> 6;
            Vs[d * 68 + j] = f2tf(V[kvb + (size_t)(kt + j) * HD + d]);
        }
        if (tid < 64)
            ms[tid] = mask[b * N_ + kt + tid] ? 0.0f : -10000.0f;
        __syncthreads();

        // S = Q K^T  (16 rows x 64 keys per warp)
        float sacc[8][4] = {};
        #pragma unroll
        for (int ks = 0; ks < 8; ks++) {
            #pragma unroll
            for (int nf = 0; nf < 8; nf++) {
                const uint32_t* bp = Ks + (nf * 8 + g) * 68 + ks * 8;
                mma_tf32(sacc[nf], qf[ks][0], qf[ks][1], qf[ks][2], qf[ks][3],
                         bp[c], bp[c + 4]);
            }
        }

        // mask + online softmax
        float t0 = -1e30f, t1 = -1e30f;
        #pragma unroll
        for (int nf = 0; nf < 8; nf++) {
            float ma = ms[nf * 8 + 2 * c];
            float mb = ms[nf * 8 + 2 * c + 1];
            sacc[nf][0] += ma; sacc[nf][1] += mb;
            sacc[nf][2] += ma; sacc[nf][3] += mb;
            t0 = fmaxf(t0, fmaxf(sacc[nf][0], sacc[nf][1]));
            t1 = fmaxf(t1, fmaxf(sacc[nf][2], sacc[nf][3]));
        }
        t0 = fmaxf(t0, __shfl_xor_sync(0xffffffffu, t0, 1));
        t0 = fmaxf(t0, __shfl_xor_sync(0xffffffffu, t0, 2));
        t1 = fmaxf(t1, __shfl_xor_sync(0xffffffffu, t1, 1));
        t1 = fmaxf(t1, __shfl_xor_sync(0xffffffffu, t1, 2));
        float mn0 = fmaxf(m0, t0), mn1 = fmaxf(m1, t1);
        float co0 = __expf(m0 - mn0), co1 = __expf(m1 - mn1);
        l0 *= co0; l1 *= co1;
        #pragma unroll
        for (int nf = 0; nf < 8; nf++) {
            of[nf][0] *= co0; of[nf][1] *= co0;
            of[nf][2] *= co1; of[nf][3] *= co1;
        }
        m0 = mn0; m1 = mn1;

        __syncthreads();   // all warps done reading Ks before P overwrite

        #pragma unroll
        for (int nf = 0; nf < 8; nf++) {
            float p0 = __expf(sacc[nf][0] - mn0);
            float p1 = __expf(sacc[nf][1] - mn0);
            float p2 = __expf(sacc[nf][2] - mn1);
            float p3 = __expf(sacc[nf][3] - mn1);
            l0 += p0 + p1; l1 += p2 + p3;
            Ks[lr0 * 68 + nf * 8 + 2 * c]           = f2tf(p0);
            Ks[lr0 * 68 + nf * 8 + 2 * c + 1]       = f2tf(p1);
            Ks[(lr0 + 8) * 68 + nf * 8 + 2 * c]     = f2tf(p2);
            Ks[(lr0 + 8) * 68 + nf * 8 + 2 * c + 1] = f2tf(p3);
        }
        __syncwarp();

        // O += P V   (A = P from smem, B = Vs transposed)
        #pragma unroll
        for (int ks = 0; ks < 8; ks++) {
            uint32_t a0 = Ks[lr0 * 68 + ks * 8 + c];
            uint32_t a1 = Ks[(lr0 + 8) * 68 + ks * 8 + c];
            uint32_t a2 = Ks[lr0 * 68 + ks * 8 + c + 4];
            uint32_t a3 = Ks[(lr0 + 8) * 68 + ks * 8 + c + 4];
            #pragma unroll
            for (int nf = 0; nf < 8; nf++) {
                const uint32_t* bp = Vs + (nf * 8 + g) * 68 + ks * 8;
                mma_tf32(of[nf], a0, a1, a2, a3, bp[c], bp[c + 4]);
            }
        }
    }

    // finalize: full row sums across quad, normalize, store
    l0 += __shfl_xor_sync(0xffffffffu, l0, 1);
    l0 += __shfl_xor_sync(0xffffffffu, l0, 2);
    l1 += __shfl_xor_sync(0xffffffffu, l1, 1);
    l1 += __shfl_xor_sync(0xffffffffu, l1, 2);
    float inv0 = 1.0f / l0, inv1 = 1.0f / l1;

    float* Op = O + ((size_t)bh * N_ + r0) * HD;
    #pragma unroll
    for (int nf = 0; nf < 8; nf++) {
        int d = nf * 8 + 2 * c;
        *reinterpret_cast<float2*>(Op + d) =
            make_float2(of[nf][0] * inv0, of[nf][1] * inv0);
        *reinterpret_cast<float2*>(Op + 8 * HD + d) =
            make_float2(of[nf][2] * inv1, of[nf][3] * inv1);
    }
}

// ---------------- Output projection GEMM (tf32 mma) --------------------------
__global__ __launch_bounds__(256) void out_gemm_t(
    const float* __restrict__ AO, const float* __restrict__ W,
    const float* __restrict__ bias, float* __restrict__ out)
{
    __shared__ __align__(16) uint32_t As[128 * 36];
    __shared__ __align__(16) uint32_t Bs[64 * 36];

    int tid  = threadIdx.x;
    int lane = tid & 31;
    int wid  = tid >> 5;
    int wM = wid >> 1, wN = wid & 1;
    int g = lane >> 2, c = lane & 3;
    int rowbase = blockIdx.y * 128;
    int colbase = blockIdx.x * 64;

    float acc[2][4][4] = {};

    for (int k0 = 0; k0 < C_; k0 += 32) {
        __syncthreads();
        #pragma unroll
        for (int p = 0; p < 4; p++) {
            int idx = tid + p * 256;
            int r = idx >> 3, k4 = idx & 7;
            int rr = rowbase + r;
            int kk = k0 + k4 * 4;
            int bb = rr >> 11, n = rr & (N_ - 1);
            int h  = kk >> 6,  d = kk & 63;
            float4 v = *reinterpret_cast<const float4*>(
                AO + (((size_t)bb * H_ + h) * N_ + n) * HD + d);
            uint4 t;
            t.x = f2tf(v.x); t.y = f2tf(v.y); t.z = f2tf(v.z); t.w = f2tf(v.w);
            *reinterpret_cast<uint4*>(As + r * 36 + k4 * 4) = t;
        }
        #pragma unroll
        for (int p = 0; p < 8; p++) {
            int idx = tid + p * 256;
            int n = idx & 63, kk = idx >> 6;
            float v = W[(size_t)(k0 + kk) * C_ + colbase + n];
            Bs[n * 36 + kk] = f2tf(v);
        }
        __syncthreads();

        #pragma unroll
        for (int ks = 0; ks < 4; ks++) {
            uint32_t a[2][4], b[4][2];
            #pragma unroll
            for (int mf = 0; mf < 2; mf++) {
                const uint32_t* ap = As + (wM * 32 + mf * 16 + g) * 36 + ks * 8;
                a[mf][0] = ap[c];
                a[mf][1] = ap[8 * 36 + c];
                a[mf][2] = ap[c + 4];
                a[mf][3] = ap[8 * 36 + c + 4];
            }
            #pragma unroll
            for (int nf = 0; nf < 4; nf++) {
                const uint32_t* bp = Bs + (wN * 32 + nf * 8 + g) * 36 + ks * 8;
                b[nf][0] = bp[c];
                b[nf][1] = bp[c + 4];
            }
            #pragma unroll
            for (int mf = 0; mf < 2; mf++)
                #pragma unroll
                for (int nf = 0; nf < 4; nf++)
                    mma_tf32(acc[mf][nf], a[mf][0], a[mf][1], a[mf][2], a[mf][3],
                             b[nf][0], b[nf][1]);
        }
    }

    #pragma unroll
    for (int mf = 0; mf < 2; mf++) {
        int r0 = rowbase + wM * 32 + mf * 16 + g;
        #pragma unroll
        for (int nf = 0; nf < 4; nf++) {
            int cc = colbase + wN * 32 + nf * 8 + 2 * c;
            float b0 = bias[cc], b1 = bias[cc + 1];
            *reinterpret_cast<float2*>(out + (size_t)r0 * C_ + cc) =
                make_float2(acc[mf][nf][0] + b0, acc[mf][nf][1] + b1);
            *reinterpret_cast<float2*>(out + (size_t)(r0 + 8) * C_ + cc) =
                make_float2(acc[mf][nf][2] + b0, acc[mf][nf][3] + b1);
        }
    }
}

// ---------------- launch -----------------------------------------------------
extern "C" void kernel_launch(void* const* d_in, const int* in_sizes, int n_in,
                              void* d_out, int out_size)
{
    const float* x    = (const float*)d_in[0];
    const int*   mask = (const int*)  d_in[1];
    const float* ln_g = (const float*)d_in[2];
    const float* ln_b = (const float*)d_in[3];
    const float* wq   = (const float*)d_in[4];
    const float* bq   = (const float*)d_in[5];
    const float* wk   = (const float*)d_in[6];
    const float* bk   = (const float*)d_in[7];
    const float* wv   = (const float*)d_in[8];
    const float* bv   = (const float*)d_in[9];
    const float* wo   = (const float*)d_in[10];
    const float* bo   = (const float*)d_in[11];
    float* out = (float*)d_out;

    float *xn, *q, *k, *v, *ao;
    cudaGetSymbolAddress((void**)&xn, g_xn);
    cudaGetSymbolAddress((void**)&q,  g_q);
    cudaGetSymbolAddress((void**)&k,  g_k);
    cudaGetSymbolAddress((void**)&v,  g_v);
    cudaGetSymbolAddress((void**)&ao, g_ao);

    ln_kernel<<<BN_, 128>>>(x, ln_g, ln_b, xn);
    qkv_gemm_t<<<dim3(C_ / 64, BN_ / 128, 3), 256>>>(xn, wq, wk, wv, bq, bk, bv, q, k, v);
    attn_t<<<dim3(N_ / 64, BH_), 128>>>(q, k, v, mask, ao);
    out_gemm_t<<<dim3(C_ / 64, BN_ / 128), 256>>>(ao, wo, bo, out);
}

// round 3
// speedup vs baseline: 2.7513x; 1.0042x over previous
#include <cuda_runtime.h>
#include <math.h>
#include <stdint.h>

#define B_  2
#define N_  2048
#define C_  512
#define H_  8
#define HD  64
#define BN_ (B_*N_)    // 4096
#define BH_ (B_*H_)    // 16

// scale = 1/(S*sqrt(d_h)) = 1/(8*sqrt(8))
#define SCALE 0.04419417382415922f

// ---------------- scratch (device globals) ----------------------------------
__device__ float g_xn[(size_t)BN_ * C_];
__device__ float g_q [(size_t)BH_ * N_ * HD];
__device__ float g_k [(size_t)BH_ * N_ * HD];
__device__ float g_v [(size_t)BH_ * N_ * HD];
__device__ float g_ao[(size_t)BH_ * N_ * HD];

// ---------------- helpers ----------------------------------------------------
__device__ __forceinline__ uint32_t f2tf(float f) {
    uint32_t u;
    asm("cvt.rna.tf32.f32 %0, %1;" : "=r"(u) : "f"(f));
    return u;
}

__device__ __forceinline__ void mma_tf32(float c[4],
    uint32_t a0, uint32_t a1, uint32_t a2, uint32_t a3,
    uint32_t b0, uint32_t b1)
{
    asm volatile(
        "mma.sync.aligned.m16n8k8.row.col.f32.tf32.tf32.f32 "
        "{%0,%1,%2,%3}, {%4,%5,%6,%7}, {%8,%9}, {%0,%1,%2,%3};"
        : "+f"(c[0]), "+f"(c[1]), "+f"(c[2]), "+f"(c[3])
        : "r"(a0), "r"(a1), "r"(a2), "r"(a3), "r"(b0), "r"(b1));
}

// ---------------- LayerNorm ---------------------------------------------------
__global__ __launch_bounds__(128) void ln_kernel(
    const float* __restrict__ x, const float* __restrict__ g,
    const float* __restrict__ bta, float* __restrict__ xn)
{
    int row = blockIdx.x;
    int tid = threadIdx.x;
    const float4* xr = reinterpret_cast<const float4*>(x + (size_t)row * C_);
    float4 v = xr[tid];
    float s  = v.x + v.y + v.z + v.w;
    float ss = v.x*v.x + v.y*v.y + v.z*v.z + v.w*v.w;
    #pragma unroll
    for (int o = 16; o; o >>= 1) {
        s  += __shfl_xor_sync(0xffffffffu, s,  o);
        ss += __shfl_xor_sync(0xffffffffu, ss, o);
    }
    __shared__ float sh[8];
    int w = tid >> 5, l = tid & 31;
    if (l == 0) { sh[w] = s; sh[4 + w] = ss; }
    __syncthreads();
    float st  = sh[0] + sh[1] + sh[2] + sh[3];
    float sst = sh[4] + sh[5] + sh[6] + sh[7];
    float mean = st * (1.0f / C_);
    float var  = sst * (1.0f / C_) - mean * mean;
    float r = rsqrtf(var + 1e-5f);
    float4 gg = reinterpret_cast<const float4*>(g)[tid];
    float4 bb = reinterpret_cast<const float4*>(bta)[tid];
    float4 o;
    o.x = (v.x - mean) * r * gg.x + bb.x;
    o.y = (v.y - mean) * r * gg.y + bb.y;
    o.z = (v.z - mean) * r * gg.z + bb.z;
    o.w = (v.w - mean) * r * gg.w + bb.w;
    reinterpret_cast<float4*>(xn + (size_t)row * C_)[tid] = o;
}

// ---------------- QKV GEMM (tf32 mma): CTA 128x64, 8 warps (4Mx2N), BK=32 ----
__global__ __launch_bounds__(256) void qkv_gemm_t(
    const float* __restrict__ A,
    const float* __restrict__ Wq, const float* __restrict__ Wk, const float* __restrict__ Wv,
    const float* __restrict__ bq, const float* __restrict__ bk, const float* __restrict__ bv,
    float* __restrict__ Q, float* __restrict__ K, float* __restrict__ V)
{
    const float* W; const float* bias; float* out;
    if (blockIdx.z == 0)      { W = Wq; bias = bq; out = Q; }
    else if (blockIdx.z == 1) { W = Wk; bias = bk; out = K; }
    else                      { W = Wv; bias = bv; out = V; }

    __shared__ __align__(16) uint32_t As[128 * 36];
    __shared__ __align__(16) uint32_t Bs[64 * 36];

    int tid  = threadIdx.x;
    int lane = tid & 31;
    int wid  = tid >> 5;
    int wM = wid >> 1, wN = wid & 1;
    int g = lane >> 2, c = lane & 3;
    int rowbase = blockIdx.y * 128;
    int colbase = blockIdx.x * 64;

    float acc[2][4][4] = {};

    for (int k0 = 0; k0 < C_; k0 += 32) {
        __syncthreads();
        // A tile 128x32: float4 loads, tf32 convert, [row][k] stride 36
        #pragma unroll
        for (int p = 0; p < 4; p++) {
            int idx = tid + p * 256;
            int r = idx >> 3, k4 = idx & 7;
            float4 v = *reinterpret_cast<const float4*>(
                A + (size_t)(rowbase + r) * C_ + k0 + k4 * 4);
            uint4 t;
            t.x = f2tf(v.x); t.y = f2tf(v.y); t.z = f2tf(v.z); t.w = f2tf(v.w);
            *reinterpret_cast<uint4*>(As + r * 36 + k4 * 4) = t;
        }
        // B tile 32x64 transposed to [n][k] stride 36 (scalar stores)
        #pragma unroll
        for (int p = 0; p < 8; p++) {
            int idx = tid + p * 256;
            int n = idx & 63, kk = idx >> 6;
            float v = W[(size_t)(k0 + kk) * C_ + colbase + n];
            Bs[n * 36 + kk] = f2tf(v);
        }
        __syncthreads();

        #pragma unroll
        for (int ks = 0; ks < 4; ks++) {
            uint32_t a[2][4], b[4][2];
            #pragma unroll
            for (int mf = 0; mf < 2; mf++) {
                const uint32_t* ap = As + (wM * 32 + mf * 16 + g) * 36 + ks * 8;
                a[mf][0] = ap[c];
                a[mf][1] = ap[8 * 36 + c];
                a[mf][2] = ap[c + 4];
                a[mf][3] = ap[8 * 36 + c + 4];
            }
            #pragma unroll
            for (int nf = 0; nf < 4; nf++) {
                const uint32_t* bp = Bs + (wN * 32 + nf * 8 + g) * 36 + ks * 8;
                b[nf][0] = bp[c];
                b[nf][1] = bp[c + 4];
            }
            #pragma unroll
            for (int mf = 0; mf < 2; mf++)
                #pragma unroll
                for (int nf = 0; nf < 4; nf++)
                    mma_tf32(acc[mf][nf], a[mf][0], a[mf][1], a[mf][2], a[mf][3],
                             b[nf][0], b[nf][1]);
        }
    }

    // epilogue: write [b,h,n,d] (col tile of 64 == head h == blockIdx.x)
    int h = blockIdx.x;
    #pragma unroll
    for (int mf = 0; mf < 2; mf++) {
        int r0 = rowbase + wM * 32 + mf * 16 + g;
        #pragma unroll
        for (int nf = 0; nf < 4; nf++) {
            int d = wN * 32 + nf * 8 + 2 * c;
            float b0 = bias[colbase + d];
            float b1 = bias[colbase + d + 1];
            {
                int r = r0;
                int bb = r >> 11, n = r & (N_ - 1);
                float2 st = make_float2(acc[mf][nf][0] + b0, acc[mf][nf][1] + b1);
                *reinterpret_cast<float2*>(
                    out + (((size_t)bb * H_ + h) * N_ + n) * HD + d) = st;
            }
            {
                int r = r0 + 8;
                int bb = r >> 11, n = r & (N_ - 1);
                float2 st = make_float2(acc[mf][nf][2] + b0, acc[mf][nf][3] + b1);
                *reinterpret_cast<float2*>(
                    out + (((size_t)bb * H_ + h) * N_ + n) * HD + d) = st;
            }
        }
    }
}

// ---------------- Flash attention (tf32 mma) ---------------------------------
// CTA: 64 queries x full key loop; 4 warps, each owns 16 query rows.
// Q frags in regs; K tile [key][d]; V tile transposed [d][key]; P aliased on K.
__global__ __launch_bounds__(128) void attn_t(
    const float* __restrict__ Q, const float* __restrict__ K,
    const float* __restrict__ V, const int* __restrict__ mask,
    float* __restrict__ O)
{
    __shared__ __align__(16) uint32_t Ks[64 * 68];   // also reused as P
    __shared__ __align__(16) uint32_t Vs[64 * 68];   // transposed [d][key]
    __shared__ float ms[64];

    int bh = blockIdx.y;
    int b  = bh >> 3;
    int qbase = blockIdx.x * 64;
    int tid  = threadIdx.x;
    int wid  = tid >> 5, lane = tid & 31;
    int g = lane >> 2, c = lane & 3;
    int lr0 = wid * 16 + g;            // local query row (0..63)
    int r0  = qbase + lr0;             // global query row

    // Q fragments: rows r0, r0+8, all 64 dims (8 k-steps), scaled, tf32
    const float* Qp = Q + ((size_t)bh * N_ + r0) * HD;
    uint32_t qf[8][4];
    #pragma unroll
    for (int ks = 0; ks < 8; ks++) {
        qf[ks][0] = f2tf(Qp[ks * 8 + c] * SCALE);
        qf[ks][1] = f2tf(Qp[8 * HD + ks * 8 + c] * SCALE);
        qf[ks][2] = f2tf(Qp[ks * 8 + c + 4] * SCALE);
        qf[ks][3] = f2tf(Qp[8 * HD + ks * 8 + c + 4] * SCALE);
    }

    float of[8][4] = {};
    float m0 = -1e30f, m1 = -1e30f, l0 = 0.0f, l1 = 0.0f;
    const size_t kvb = (size_t)bh * N_ * HD;

    for (int kt = 0; kt < N_; kt += 64) {
        __syncthreads();   // prev-tile PV reads done before overwrite
        // K tile: [key][d], stride 68, float4 + tf32
        #pragma unroll
        for (int p = 0; p < 8; p++) {
            int idx = tid + p * 128;
            int j = idx >> 4, d4 = idx & 15;
            float4 v = *reinterpret_cast<const float4*>(
                K + kvb + (size_t)(kt + j) * HD + d4 * 4);
            uint4 t;
            t.x = f2tf(v.x); t.y = f2tf(v.y); t.z = f2tf(v.z); t.w = f2tf(v.w);
            *reinterpret_cast<uint4*>(Ks + j * 68 + d4 * 4) = t;
        }
        // V tile transposed: Vs[d][key], scalar stores
        #pragma unroll
        for (int p = 0; p < 32; p++) {
            int idx = tid + p * 128;
            int d = idx & 63, j = idx >> 6;
            Vs[d * 68 + j] = f2tf(V[kvb + (size_t)(kt + j) * HD + d]);
        }
        if (tid < 64)
            ms[tid] = mask[b * N_ + kt + tid] ? 0.0f : -10000.0f;
        __syncthreads();

        // S = Q K^T  (16 rows x 64 keys per warp)
        float sacc[8][4] = {};
        #pragma unroll
        for (int ks = 0; ks < 8; ks++) {
            #pragma unroll
            for (int nf = 0; nf < 8; nf++) {
                const uint32_t* bp = Ks + (nf * 8 + g) * 68 + ks * 8;
                mma_tf32(sacc[nf], qf[ks][0], qf[ks][1], qf[ks][2], qf[ks][3],
                         bp[c], bp[c + 4]);
            }
        }

        // mask + online softmax
        float t0 = -1e30f, t1 = -1e30f;
        #pragma unroll
        for (int nf = 0; nf < 8; nf++) {
            float ma = ms[nf * 8 + 2 * c];
            float mb = ms[nf * 8 + 2 * c + 1];
            sacc[nf][0] += ma; sacc[nf][1] += mb;
            sacc[nf][2] += ma; sacc[nf][3] += mb;
            t0 = fmaxf(t0, fmaxf(sacc[nf][0], sacc[nf][1]));
            t1 = fmaxf(t1, fmaxf(sacc[nf][2], sacc[nf][3]));
        }
        t0 = fmaxf(t0, __shfl_xor_sync(0xffffffffu, t0, 1));
        t0 = fmaxf(t0, __shfl_xor_sync(0xffffffffu, t0, 2));
        t1 = fmaxf(t1, __shfl_xor_sync(0xffffffffu, t1, 1));
        t1 = fmaxf(t1, __shfl_xor_sync(0xffffffffu, t1, 2));
        float mn0 = fmaxf(m0, t0), mn1 = fmaxf(m1, t1);
        float co0 = __expf(m0 - mn0), co1 = __expf(m1 - mn1);
        l0 *= co0; l1 *= co1;
        #pragma unroll
        for (int nf = 0; nf < 8; nf++) {
            of[nf][0] *= co0; of[nf][1] *= co0;
            of[nf][2] *= co1; of[nf][3] *= co1;
        }
        m0 = mn0; m1 = mn1;

        __syncthreads();   // all warps done reading Ks before P overwrite

        #pragma unroll
        for (int nf = 0; nf < 8; nf++) {
            float p0 = __expf(sacc[nf][0] - mn0);
            float p1 = __expf(sacc[nf][1] - mn0);
            float p2 = __expf(sacc[nf][2] - mn1);
            float p3 = __expf(sacc[nf][3] - mn1);
            l0 += p0 + p1; l1 += p2 + p3;
            Ks[lr0 * 68 + nf * 8 + 2 * c]           = f2tf(p0);
            Ks[lr0 * 68 + nf * 8 + 2 * c + 1]       = f2tf(p1);
            Ks[(lr0 + 8) * 68 + nf * 8 + 2 * c]     = f2tf(p2);
            Ks[(lr0 + 8) * 68 + nf * 8 + 2 * c + 1] = f2tf(p3);
        }
        __syncwarp();

        // O += P V   (A = P from smem, B = Vs transposed)
        #pragma unroll
        for (int ks = 0; ks < 8; ks++) {
            uint32_t a0 = Ks[lr0 * 68 + ks * 8 + c];
            uint32_t a1 = Ks[(lr0 + 8) * 68 + ks * 8 + c];
            uint32_t a2 = Ks[lr0 * 68 + ks * 8 + c + 4];
            uint32_t a3 = Ks[(lr0 + 8) * 68 + ks * 8 + c + 4];
            #pragma unroll
            for (int nf = 0; nf < 8; nf++) {
                const uint32_t* bp = Vs + (nf * 8 + g) * 68 + ks * 8;
                mma_tf32(of[nf], a0, a1, a2, a3, bp[c], bp[c + 4]);
            }
        }
    }

    // finalize: full row sums across quad, normalize, store
    l0 += __shfl_xor_sync(0xffffffffu, l0, 1);
    l0 += __shfl_xor_sync(0xffffffffu, l0, 2);
    l1 += __shfl_xor_sync(0xffffffffu, l1, 1);
    l1 += __shfl_xor_sync(0xffffffffu, l1, 2);
    float inv0 = 1.0f / l0, inv1 = 1.0f / l1;

    float* Op = O + ((size_t)bh * N_ + r0) * HD;
    #pragma unroll
    for (int nf = 0; nf < 8; nf++) {
        int d = nf * 8 + 2 * c;
        *reinterpret_cast<float2*>(Op + d) =
            make_float2(of[nf][0] * inv0, of[nf][1] * inv0);
        *reinterpret_cast<float2*>(Op + 8 * HD + d) =
            make_float2(of[nf][2] * inv1, of[nf][3] * inv1);
    }
}

// ---------------- Output projection GEMM (tf32 mma) --------------------------
__global__ __launch_bounds__(256) void out_gemm_t(
    const float* __restrict__ AO, const float* __restrict__ W,
    const float* __restrict__ bias, float* __restrict__ out)
{
    __shared__ __align__(16) uint32_t As[128 * 36];
    __shared__ __align__(16) uint32_t Bs[64 * 36];

    int tid  = threadIdx.x;
    int lane = tid & 31;
    int wid  = tid >> 5;
    int wM = wid >> 1, wN = wid & 1;
    int g = lane >> 2, c = lane & 3;
    int rowbase = blockIdx.y * 128;
    int colbase = blockIdx.x * 64;

    float acc[2][4][4] = {};

    for (int k0 = 0; k0 < C_; k0 += 32) {
        __syncthreads();
        #pragma unroll
        for (int p = 0; p < 4; p++) {
            int idx = tid + p * 256;
            int r = idx >> 3, k4 = idx & 7;
            int rr = rowbase + r;
            int kk = k0 + k4 * 4;
            int bb = rr >> 11, n = rr & (N_ - 1);
            int h  = kk >> 6,  d = kk & 63;
            float4 v = *reinterpret_cast<const float4*>(
                AO + (((size_t)bb * H_ + h) * N_ + n) * HD + d);
            uint4 t;
            t.x = f2tf(v.x); t.y = f2tf(v.y); t.z = f2tf(v.z); t.w = f2tf(v.w);
            *reinterpret_cast<uint4*>(As + r * 36 + k4 * 4) = t;
        }
        #pragma unroll
        for (int p = 0; p < 8; p++) {
            int idx = tid + p * 256;
            int n = idx & 63, kk = idx >> 6;
            float v = W[(size_t)(k0 + kk) * C_ + colbase + n];
            Bs[n * 36 + kk] = f2tf(v);
        }
        __syncthreads();

        #pragma unroll
        for (int ks = 0; ks < 4; ks++) {
            uint32_t a[2][4], b[4][2];
            #pragma unroll
            for (int mf = 0; mf < 2; mf++) {
                const uint32_t* ap = As + (wM * 32 + mf * 16 + g) * 36 + ks * 8;
                a[mf][0] = ap[c];
                a[mf][1] = ap[8 * 36 + c];
                a[mf][2] = ap[c + 4];
                a[mf][3] = ap[8 * 36 + c + 4];
            }
            #pragma unroll
            for (int nf = 0; nf < 4; nf++) {
                const uint32_t* bp = Bs + (wN * 32 + nf * 8 + g) * 36 + ks * 8;
                b[nf][0] = bp[c];
                b[nf][1] = bp[c + 4];
            }
            #pragma unroll
            for (int mf = 0; mf < 2; mf++)
                #pragma unroll
                for (int nf = 0; nf < 4; nf++)
                    mma_tf32(acc[mf][nf], a[mf][0], a[mf][1], a[mf][2], a[mf][3],
                             b[nf][0], b[nf][1]);
        }
    }

    #pragma unroll
    for (int mf = 0; mf < 2; mf++) {
        int r0 = rowbase + wM * 32 + mf * 16 + g;
        #pragma unroll
        for (int nf = 0; nf < 4; nf++) {
            int cc = colbase + wN * 32 + nf * 8 + 2 * c;
            float b0 = bias[cc], b1 = bias[cc + 1];
            *reinterpret_cast<float2*>(out + (size_t)r0 * C_ + cc) =
                make_float2(acc[mf][nf][0] + b0, acc[mf][nf][1] + b1);
            *reinterpret_cast<float2*>(out + (size_t)(r0 + 8) * C_ + cc) =
                make_float2(acc[mf][nf][2] + b0, acc[mf][nf][3] + b1);
        }
    }
}

// ---------------- launch -----------------------------------------------------
extern "C" void kernel_launch(void* const* d_in, const int* in_sizes, int n_in,
                              void* d_out, int out_size)
{
    const float* x    = (const float*)d_in[0];
    const int*   mask = (const int*)  d_in[1];
    const float* ln_g = (const float*)d_in[2];
    const float* ln_b = (const float*)d_in[3];
    const float* wq   = (const float*)d_in[4];
    const float* bq   = (const float*)d_in[5];
    const float* wk   = (const float*)d_in[6];
    const float* bk   = (const float*)d_in[7];
    const float* wv   = (const float*)d_in[8];
    const float* bv   = (const float*)d_in[9];
    const float* wo   = (const float*)d_in[10];
    const float* bo   = (const float*)d_in[11];
    float* out = (float*)d_out;

    float *xn, *q, *k, *v, *ao;
    cudaGetSymbolAddress((void**)&xn, g_xn);
    cudaGetSymbolAddress((void**)&q,  g_q);
    cudaGetSymbolAddress((void**)&k,  g_k);
    cudaGetSymbolAddress((void**)&v,  g_v);
    cudaGetSymbolAddress((void**)&ao, g_ao);

    ln_kernel<<<BN_, 128>>>(x, ln_g, ln_b, xn);
    qkv_gemm_t<<<dim3(C_ / 64, BN_ / 128, 3), 256>>>(xn, wq, wk, wv, bq, bk, bv, q, k, v);
    attn_t<<<dim3(N_ / 64, BH_), 128>>>(q, k, v, mask, ao);
    out_gemm_t<<<dim3(C_ / 64, BN_ / 128), 256>>>(ao, wo, bo, out);
}

// round 5
// speedup vs baseline: 3.8575x; 1.4021x over previous
#include <cuda_runtime.h>
#include <stdint.h>

#define B_  2
#define N_  2048
#define C_  512
#define H_  8
#define HD  64
#define BN_ (B_*N_)
#define BH_ (B_*H_)
#define SCALE 0.04419417382415922f

__device__ float g_xn[(size_t)BN_ * C_];
__device__ float g_q [(size_t)BH_ * N_ * HD];   // [b,h,n,d] scaled+tf32
__device__ float g_k [(size_t)BH_ * N_ * HD];   // [b,h,n,d] tf32
__device__ float g_v [(size_t)BH_ * N_ * HD];   // [b,h,d,n] transposed tf32
__device__ float g_ao[(size_t)BH_ * N_ * HD];   // [b,h,n,d] tf32
__device__ float g_wt[4][(size_t)C_ * C_];      // transposed [n][k] tf32

__device__ __forceinline__ uint32_t f2tf(float f) {
    uint32_t u; asm("cvt.rna.tf32.f32 %0, %1;" : "=r"(u) : "f"(f)); return u;
}
__device__ __forceinline__ float f2tff(float f) { return __uint_as_float(f2tf(f)); }

__device__ __forceinline__ void mma_tf32(float c[4],
    uint32_t a0, uint32_t a1, uint32_t a2, uint32_t a3, uint32_t b0, uint32_t b1)
{
    asm volatile(
        "mma.sync.aligned.m16n8k8.row.col.f32.tf32.tf32.f32 "
        "{%0,%1,%2,%3}, {%4,%5,%6,%7}, {%8,%9}, {%0,%1,%2,%3};"
        : "+f"(c[0]), "+f"(c[1]), "+f"(c[2]), "+f"(c[3])
        : "r"(a0), "r"(a1), "r"(a2), "r"(a3), "r"(b0), "r"(b1));
}
__device__ __forceinline__ void cp16(uint32_t dst, const void* src) {
    asm volatile("cp.async.cg.shared.global [%0], [%1], 16;" :: "r"(dst), "l"(src));
}
#define CPCOMMIT() asm volatile("cp.async.commit_group;")
#define CPWAIT0()  asm volatile("cp.async.wait_group 0;")

// ---------------- weight prep: transpose + tf32 round -------------------------
__global__ __launch_bounds__(256) void prep_w(
    const float* __restrict__ wq, const float* __restrict__ wk,
    const float* __restrict__ wv, const float* __restrict__ wo)
{
    __shared__ float tile[32][33];
    int m = blockIdx.z;
    const float* s = (m == 0) ? wq : (m == 1) ? wk : (m == 2) ? wv : wo;
    int x0 = blockIdx.x * 32, y0 = blockIdx.y * 32;
    int tx = threadIdx.x & 31, ty = threadIdx.x >> 5;
    #pragma unroll
    for (int i = 0; i < 4; i++)
        tile[ty + 8 * i][tx] = s[(size_t)(y0 + ty + 8 * i) * C_ + x0 + tx];
    __syncthreads();
    #pragma unroll
    for (int i = 0; i < 4; i++)
        g_wt[m][(size_t)(x0 + ty + 8 * i) * C_ + y0 + tx] = f2tff(tile[tx][ty + 8 * i]);
}

// ---------------- LayerNorm (tf32-rounded output) ----------------------------
__global__ __launch_bounds__(128) void ln_kernel(
    const float* __restrict__ x, const float* __restrict__ g,
    const float* __restrict__ bta, float* __restrict__ xn)
{
    int row = blockIdx.x, tid = threadIdx.x;
    float4 v = reinterpret_cast<const float4*>(x + (size_t)row * C_)[tid];
    float s = v.x + v.y + v.z + v.w;
    float ss = v.x*v.x + v.y*v.y + v.z*v.z + v.w*v.w;
    #pragma unroll
    for (int o = 16; o; o >>= 1) {
        s  += __shfl_xor_sync(~0u, s,  o);
        ss += __shfl_xor_sync(~0u, ss, o);
    }
    __shared__ float sh[8];
    int w = tid >> 5, l = tid & 31;
    if (l == 0) { sh[w] = s; sh[4 + w] = ss; }
    __syncthreads();
    float st = sh[0]+sh[1]+sh[2]+sh[3], sst = sh[4]+sh[5]+sh[6]+sh[7];
    float mean = st * (1.0f / C_);
    float var  = sst * (1.0f / C_) - mean * mean;
    float r = rsqrtf(var + 1e-5f);
    float4 gg = reinterpret_cast<const float4*>(g)[tid];
    float4 bb = reinterpret_cast<const float4*>(bta)[tid];
    float4 o;
    o.x = f2tff((v.x - mean) * r * gg.x + bb.x);
    o.y = f2tff((v.y - mean) * r * gg.y + bb.y);
    o.z = f2tff((v.z - mean) * r * gg.z + bb.z);
    o.w = f2tff((v.w - mean) * r * gg.w + bb.w);
    reinterpret_cast<float4*>(xn + (size_t)row * C_)[tid] = o;
}

// ============================================================================
// GEMM: 64x64 CTA tile, BK=32, 128 thr, 4 warps (2Mx2N, warp 32x32).
// Smem layout = round-2 verified: [row][k] stride 36, double buffered.
// A-frag: ap = buf*2304 + row*36 + ks*8 ; a0=ap[c] a1=ap[8*36+c] a2=ap[c+4] a3=ap[8*36+c+4]
// B-frag: bp = buf*2304 + n*36   + ks*8 ; b0=bp[c] b1=bp[c+4]
// ============================================================================
__device__ __forceinline__ void gemm_frag_compute(
    const uint32_t* sA, const uint32_t* sB, int buf,
    int wM, int wN, int g, int c, float acc[2][4][4])
{
    #pragma unroll
    for (int ks = 0; ks < 4; ks++) {
        uint32_t a[2][4], b[4][2];
        #pragma unroll
        for (int mf = 0; mf < 2; mf++) {
            const uint32_t* ap = sA + buf * 2304 + (wM * 32 + mf * 16 + g) * 36 + ks * 8;
            a[mf][0] = ap[c];
            a[mf][1] = ap[8 * 36 + c];
            a[mf][2] = ap[c + 4];
            a[mf][3] = ap[8 * 36 + c + 4];
        }
        #pragma unroll
        for (int nf = 0; nf < 4; nf++) {
            const uint32_t* bp = sB + buf * 2304 + (wN * 32 + nf * 8 + g) * 36 + ks * 8;
            b[nf][0] = bp[c];
            b[nf][1] = bp[c + 4];
        }
        #pragma unroll
        for (int mf = 0; mf < 2; mf++)
            #pragma unroll
            for (int nf = 0; nf < 4; nf++)
                mma_tf32(acc[mf][nf], a[mf][0], a[mf][1], a[mf][2], a[mf][3],
                         b[nf][0], b[nf][1]);
    }
}

__global__ __launch_bounds__(128) void qkv_gemm(
    const float* __restrict__ A,
    const float* __restrict__ bq, const float* __restrict__ bk, const float* __restrict__ bv,
    float* __restrict__ Q, float* __restrict__ K, float* __restrict__ V)
{
    __shared__ __align__(16) uint32_t sA[2 * 2304];
    __shared__ __align__(16) uint32_t sB[2 * 2304];
    uint32_t aB = (uint32_t)__cvta_generic_to_shared(sA);
    uint32_t bB = (uint32_t)__cvta_generic_to_shared(sB);

    int z = blockIdx.z;
    const float* Wt = &g_wt[z][0];
    const float* bias = (z == 0) ? bq : (z == 1) ? bk : bv;

    int tid = threadIdx.x, lane = tid & 31, wid = tid >> 5;
    int wM = wid >> 1, wN = wid & 1, g = lane >> 2, c = lane & 3;
    int rowbase = blockIdx.y * 64, colbase = blockIdx.x * 64;

    // prologue: tile 0 into buf 0
    #pragma unroll
    for (int p = 0; p < 4; p++) {
        int idx = tid + p * 128;
        int r = idx >> 3, k4 = idx & 7;
        uint32_t off = (uint32_t)(r * 36 + k4 * 4) * 4;
        cp16(aB + off, A  + (size_t)(rowbase + r) * C_ + k4 * 4);
        cp16(bB + off, Wt + (size_t)(colbase + r) * C_ + k4 * 4);
    }
    CPCOMMIT();

    float acc[2][4][4] = {};
    for (int t = 0; t < 16; t++) {
        int buf = t & 1;
        CPWAIT0();
        __syncthreads();
        if (t < 15) {
            int k0 = (t + 1) * 32;
            uint32_t bo = (uint32_t)((buf ^ 1) * 2304) * 4;
            #pragma unroll
            for (int p = 0; p < 4; p++) {
                int idx = tid + p * 128;
                int r = idx >> 3, k4 = idx & 7;
                uint32_t off = bo + (uint32_t)(r * 36 + k4 * 4) * 4;
                cp16(aB + off, A  + (size_t)(rowbase + r) * C_ + k0 + k4 * 4);
                cp16(bB + off, Wt + (size_t)(colbase + r) * C_ + k0 + k4 * 4);
            }
            CPCOMMIT();
        }
        gemm_frag_compute(sA, sB, buf, wM, wN, g, c, acc);
    }

    int h = blockIdx.x;
    int bb = rowbase >> 11, nbase = rowbase & (N_ - 1);
    if (z != 2) {
        float* out = z ? K : Q;
        float sc = z ? 1.0f : SCALE;
        #pragma unroll
        for (int mf = 0; mf < 2; mf++) {
            int rl = wM * 32 + mf * 16 + g;
            #pragma unroll
            for (int nf = 0; nf < 4; nf++) {
                int d = wN * 32 + nf * 8 + 2 * c;
                float b0 = bias[colbase + d], b1 = bias[colbase + d + 1];
                float* o0 = out + (((size_t)bb * H_ + h) * N_ + nbase + rl) * HD + d;
                float* o1 = out + (((size_t)bb * H_ + h) * N_ + nbase + rl + 8) * HD + d;
                *reinterpret_cast<float2*>(o0) =
                    make_float2(f2tff((acc[mf][nf][0] + b0) * sc), f2tff((acc[mf][nf][1] + b1) * sc));
                *reinterpret_cast<float2*>(o1) =
                    make_float2(f2tff((acc[mf][nf][2] + b0) * sc), f2tff((acc[mf][nf][3] + b1) * sc));
            }
        }
    } else {
        // V: transpose through smem -> [b,h,d,n]
        __syncthreads();
        float* tb = (float*)sA;   // [64 dims][65] floats, 4160 <= 4608 words
        #pragma unroll
        for (int mf = 0; mf < 2; mf++) {
            int rl = wM * 32 + mf * 16 + g;
            #pragma unroll
            for (int nf = 0; nf < 4; nf++) {
                int d = wN * 32 + nf * 8 + 2 * c;
                float b0 = bias[colbase + d], b1 = bias[colbase + d + 1];
                tb[d * 65 + rl]           = f2tff(acc[mf][nf][0] + b0);
                tb[(d + 1) * 65 + rl]     = f2tff(acc[mf][nf][1] + b1);
                tb[d * 65 + rl + 8]       = f2tff(acc[mf][nf][2] + b0);
                tb[(d + 1) * 65 + rl + 8] = f2tff(acc[mf][nf][3] + b1);
            }
        }
        __syncthreads();
        #pragma unroll
        for (int p = 0; p < 8; p++) {
            int idx = tid + p * 128;
            int d = idx >> 4, n4 = idx & 15;
            float4 val = make_float4(tb[d * 65 + n4 * 4],     tb[d * 65 + n4 * 4 + 1],
                                     tb[d * 65 + n4 * 4 + 2], tb[d * 65 + n4 * 4 + 3]);
            *reinterpret_cast<float4*>(
                V + (((size_t)bb * H_ + h) * HD + d) * N_ + nbase + n4 * 4) = val;
        }
    }
}

// ============================================================================
// Flash attention: 128 q/CTA, 8 warps x 16 q-rows, 64-key tiles,
// round-2 verified smem layouts (stride 68), cp.async double-buffered K/V,
// dedicated warp-private P buffer (syncwarp only).
// smem words: Ks 2*4352, Vs 2*4352, Ps 128*68=8704, ms 128  -> 26240 (102.5 KB)
// ============================================================================
#define AKS(buf) ((buf) * 4352)
#define AVS(buf) (8704 + (buf) * 4352)
#define APS      17408
#define AMS      26112
#define ATTN_SMB (26240 * 4)

__global__ __launch_bounds__(256, 2) void attn_t(
    const float* __restrict__ Q, const float* __restrict__ K,
    const float* __restrict__ Vt, const int* __restrict__ mask,
    float* __restrict__ O)
{
    extern __shared__ uint32_t sm[];
    float* ms = (float*)(sm + AMS);
    uint32_t sb = (uint32_t)__cvta_generic_to_shared(sm);

    int bh = blockIdx.y, b = bh >> 3;
    int qbase = blockIdx.x * 128;
    int tid = threadIdx.x, wid = tid >> 5, lane = tid & 31;
    int g = lane >> 2, c = lane & 3;
    int lr0 = wid * 16 + g;
    int r0  = qbase + lr0;
    const size_t kvb = (size_t)bh * N_ * HD;

    // Q fragments: pre-scaled pre-rounded, raw bits
    const uint32_t* Qp = reinterpret_cast<const uint32_t*>(Q + ((size_t)bh * N_ + r0) * HD);
    uint32_t qf[8][4];
    #pragma unroll
    for (int ks = 0; ks < 8; ks++) {
        qf[ks][0] = Qp[ks * 8 + c];
        qf[ks][1] = Qp[8 * HD + ks * 8 + c];
        qf[ks][2] = Qp[ks * 8 + c + 4];
        qf[ks][3] = Qp[8 * HD + ks * 8 + c + 4];
    }

    // prologue: tile 0 into buf 0; K [key][d] stride 68, V [d][key] stride 68
    #pragma unroll
    for (int p = 0; p < 4; p++) {
        int idx = tid + p * 256;
        int key = idx >> 4, d4 = idx & 15;
        cp16(sb + (uint32_t)(AKS(0) + key * 68 + d4 * 4) * 4,
             K + kvb + (size_t)key * HD + d4 * 4);
    }
    #pragma unroll
    for (int p = 0; p < 4; p++) {
        int idx = tid + p * 256;
        int d = idx >> 4, k4 = idx & 15;
        cp16(sb + (uint32_t)(AVS(0) + d * 68 + k4 * 4) * 4,
             Vt + kvb + (size_t)d * N_ + k4 * 4);
    }
    CPCOMMIT();
    if (tid < 64) ms[tid] = mask[b * N_ + tid] ? 0.0f : -10000.0f;

    float of[8][4] = {};
    float m0 = -1e30f, m1 = -1e30f, l0 = 0.0f, l1 = 0.0f;

    for (int t = 0; t < 32; t++) {
        int buf = t & 1;
        CPWAIT0();
        __syncthreads();
        int mreg = 0;
        if (t < 31) {
            int kn = (t + 1) * 64;
            #pragma unroll
            for (int p = 0; p < 4; p++) {
                int idx = tid + p * 256;
                int key = idx >> 4, d4 = idx & 15;
                cp16(sb + (uint32_t)(AKS(buf ^ 1) + key * 68 + d4 * 4) * 4,
                     K + kvb + (size_t)(kn + key) * HD + d4 * 4);
            }
            #pragma unroll
            for (int p = 0; p < 4; p++) {
                int idx = tid + p * 256;
                int d = idx >> 4, k4 = idx & 15;
                cp16(sb + (uint32_t)(AVS(buf ^ 1) + d * 68 + k4 * 4) * 4,
                     Vt + kvb + (size_t)d * N_ + kn + k4 * 4);
            }
            CPCOMMIT();
            if (tid < 64) mreg = mask[b * N_ + kn + tid];
        }

        // S = Q K^T
        const uint32_t* Kb = sm + AKS(buf);
        float sacc[8][4] = {};
        #pragma unroll
        for (int ks = 0; ks < 8; ks++) {
            #pragma unroll
            for (int nf = 0; nf < 8; nf++) {
                const uint32_t* bp = Kb + (nf * 8 + g) * 68 + ks * 8;
                mma_tf32(sacc[nf], qf[ks][0], qf[ks][1], qf[ks][2], qf[ks][3],
                         bp[c], bp[c + 4]);
            }
        }

        // mask + online softmax
        const float* msp = ms + buf * 64;
        float t0 = -1e30f, t1 = -1e30f;
        #pragma unroll
        for (int nf = 0; nf < 8; nf++) {
            float ma = msp[nf * 8 + 2 * c], mb = msp[nf * 8 + 2 * c + 1];
            sacc[nf][0] += ma; sacc[nf][1] += mb;
            sacc[nf][2] += ma; sacc[nf][3] += mb;
            t0 = fmaxf(t0, fmaxf(sacc[nf][0], sacc[nf][1]));
            t1 = fmaxf(t1, fmaxf(sacc[nf][2], sacc[nf][3]));
        }
        t0 = fmaxf(t0, __shfl_xor_sync(~0u, t0, 1));
        t0 = fmaxf(t0, __shfl_xor_sync(~0u, t0, 2));
        t1 = fmaxf(t1, __shfl_xor_sync(~0u, t1, 1));
        t1 = fmaxf(t1, __shfl_xor_sync(~0u, t1, 2));
        float mn0 = fmaxf(m0, t0), mn1 = fmaxf(m1, t1);
        float co0 = __expf(m0 - mn0), co1 = __expf(m1 - mn1);
        l0 *= co0; l1 *= co1;
        #pragma unroll
        for (int nf = 0; nf < 8; nf++) {
            of[nf][0] *= co0; of[nf][1] *= co0;
            of[nf][2] *= co1; of[nf][3] *= co1;
        }
        m0 = mn0; m1 = mn1;

        // P -> warp-private smem rows (tf32 bits), round-2 verified pattern
        uint32_t* Ps = sm + APS;
        #pragma unroll
        for (int nf = 0; nf < 8; nf++) {
            float p0 = __expf(sacc[nf][0] - mn0);
            float p1 = __expf(sacc[nf][1] - mn0);
            float p2 = __expf(sacc[nf][2] - mn1);
            float p3 = __expf(sacc[nf][3] - mn1);
            l0 += p0 + p1; l1 += p2 + p3;
            Ps[lr0 * 68 + nf * 8 + 2 * c]           = f2tf(p0);
            Ps[lr0 * 68 + nf * 8 + 2 * c + 1]       = f2tf(p1);
            Ps[(lr0 + 8) * 68 + nf * 8 + 2 * c]     = f2tf(p2);
            Ps[(lr0 + 8) * 68 + nf * 8 + 2 * c + 1] = f2tf(p3);
        }
        __syncwarp();

        // O += P V
        const uint32_t* Vb = sm + AVS(buf);
        #pragma unroll
        for (int ks = 0; ks < 8; ks++) {
            uint32_t a0 = Ps[lr0 * 68 + ks * 8 + c];
            uint32_t a1 = Ps[(lr0 + 8) * 68 + ks * 8 + c];
            uint32_t a2 = Ps[lr0 * 68 + ks * 8 + c + 4];
            uint32_t a3 = Ps[(lr0 + 8) * 68 + ks * 8 + c + 4];
            #pragma unroll
            for (int nf = 0; nf < 8; nf++) {
                const uint32_t* bp = Vb + (nf * 8 + g) * 68 + ks * 8;
                mma_tf32(of[nf], a0, a1, a2, a3, bp[c], bp[c + 4]);
            }
        }
        if (t < 31 && tid < 64)
            ms[(buf ^ 1) * 64 + tid] = mreg ? 0.0f : -10000.0f;
    }

    l0 += __shfl_xor_sync(~0u, l0, 1); l0 += __shfl_xor_sync(~0u, l0, 2);
    l1 += __shfl_xor_sync(~0u, l1, 1); l1 += __shfl_xor_sync(~0u, l1, 2);
    float inv0 = 1.0f / l0, inv1 = 1.0f / l1;
    float* Op = O + ((size_t)bh * N_ + r0) * HD;
    #pragma unroll
    for (int nf = 0; nf < 8; nf++) {
        int d = nf * 8 + 2 * c;
        *reinterpret_cast<float2*>(Op + d) =
            make_float2(f2tff(of[nf][0] * inv0), f2tff(of[nf][1] * inv0));
        *reinterpret_cast<float2*>(Op + 8 * HD + d) =
            make_float2(f2tff(of[nf][2] * inv1), f2tff(of[nf][3] * inv1));
    }
}

// ---------------- Output projection -------------------------------------------
__global__ __launch_bounds__(128) void out_gemm(
    const float* __restrict__ AO, const float* __restrict__ bias, float* __restrict__ out)
{
    __shared__ __align__(16) uint32_t sA[2 * 2304];
    __shared__ __align__(16) uint32_t sB[2 * 2304];
    uint32_t aB = (uint32_t)__cvta_generic_to_shared(sA);
    uint32_t bB = (uint32_t)__cvta_generic_to_shared(sB);
    const float* Wt = &g_wt[3][0];

    int tid = threadIdx.x, lane = tid & 31, wid = tid >> 5;
    int wM = wid >> 1, wN = wid & 1, g = lane >> 2, c = lane & 3;
    int rowbase = blockIdx.y * 64, colbase = blockIdx.x * 64;
    int bb = rowbase >> 11, nbase = rowbase & (N_ - 1);

    #pragma unroll
    for (int p = 0; p < 4; p++) {
        int idx = tid + p * 128;
        int r = idx >> 3, k4 = idx & 7;
        int k = k4 * 4, h = k >> 6, d = k & 63;
        uint32_t off = (uint32_t)(r * 36 + k4 * 4) * 4;
        cp16(aB + off, AO + (((size_t)bb * H_ + h) * N_ + nbase + r) * HD + d);
        cp16(bB + off, Wt + (size_t)(colbase + r) * C_ + k4 * 4);
    }
    CPCOMMIT();

    float acc[2][4][4] = {};
    for (int t = 0; t < 16; t++) {
        int buf = t & 1;
        CPWAIT0();
        __syncthreads();
        if (t < 15) {
            int k0 = (t + 1) * 32;
            uint32_t bo = (uint32_t)((buf ^ 1) * 2304) * 4;
            #pragma unroll
            for (int p = 0; p < 4; p++) {
                int idx = tid + p * 128;
                int r = idx >> 3, k4 = idx & 7;
                int k = k0 + k4 * 4, h = k >> 6, d = k & 63;
                uint32_t off = bo + (uint32_t)(r * 36 + k4 * 4) * 4;
                cp16(aB + off, AO + (((size_t)bb * H_ + h) * N_ + nbase + r) * HD + d);
                cp16(bB + off, Wt + (size_t)(colbase + r) * C_ + k0 + k4 * 4);
            }
            CPCOMMIT();
        }
        gemm_frag_compute(sA, sB, buf, wM, wN, g, c, acc);
    }

    #pragma unroll
    for (int mf = 0; mf < 2; mf++) {
        int r = rowbase + wM * 32 + mf * 16 + g;
        #pragma unroll
        for (int nf = 0; nf < 4; nf++) {
            int cc = colbase + wN * 32 + nf * 8 + 2 * c;
            float b0 = bias[cc], b1 = bias[cc + 1];
            *reinterpret_cast<float2*>(out + (size_t)r * C_ + cc) =
                make_float2(acc[mf][nf][0] + b0, acc[mf][nf][1] + b1);
            *reinterpret_cast<float2*>(out + (size_t)(r + 8) * C_ + cc) =
                make_float2(acc[mf][nf][2] + b0, acc[mf][nf][3] + b1);
        }
    }
}

// ---------------- launch -------------------------------------------------------
extern "C" void kernel_launch(void* const* d_in, const int* in_sizes, int n_in,
                              void* d_out, int out_size)
{
    const float* x    = (const float*)d_in[0];
    const int*   mask = (const int*)  d_in[1];
    const float* ln_g = (const float*)d_in[2];
    const float* ln_b = (const float*)d_in[3];
    const float* wq   = (const float*)d_in[4];
    const float* bq   = (const float*)d_in[5];
    const float* wk   = (const float*)d_in[6];
    const float* bk   = (const float*)d_in[7];
    const float* wv   = (const float*)d_in[8];
    const float* bv   = (const float*)d_in[9];
    const float* wo   = (const float*)d_in[10];
    const float* bo   = (const float*)d_in[11];
    float* out = (float*)d_out;

    float *xn, *q, *k, *v, *ao;
    cudaGetSymbolAddress((void**)&xn, g_xn);
    cudaGetSymbolAddress((void**)&q,  g_q);
    cudaGetSymbolAddress((void**)&k,  g_k);
    cudaGetSymbolAddress((void**)&v,  g_v);
    cudaGetSymbolAddress((void**)&ao, g_ao);

    cudaFuncSetAttribute(attn_t, cudaFuncAttributeMaxDynamicSharedMemorySize, ATTN_SMB);

    prep_w<<<dim3(16, 16, 4), 256>>>(wq, wk, wv, wo);
    ln_kernel<<<BN_, 128>>>(x, ln_g, ln_b, xn);
    qkv_gemm<<<dim3(C_ / 64, BN_ / 64, 3), 128>>>(xn, bq, bk, bv, q, k, v);
    attn_t<<<dim3(N_ / 128, BH_), 256, ATTN_SMB>>>(q, k, v, mask, ao);
    out_gemm<<<dim3(C_ / 64, BN_ / 64), 128>>>(ao, bo, out);
}